// round 15
// baseline (speedup 1.0000x reference)
#include <cuda_runtime.h>
#include <cuda_bf16.h>
#include <cuda_fp16.h>
#include <cstdint>

#define H 8
#define L 4096
#define D 64
#define NB 64
#define TOPK 16
#define NEG_BIG (-1e30f)
#define KVP 16   // kv partials per head

// ---------------- scratch ----------------
__device__ float g_pq[H * NB * D];
__device__ float g_pk[H * NB * D];
__device__ float g_kvp[H * KVP * D * D];
__device__ float g_M[H * D * D];
__device__ float g_ksum[H * D];
__device__ float g_ksum_part[H * NB * D];
__device__ __half g_oparth[H * NB * 2 * 64 * D];  // split-K partial O (normalized, fp16)
__device__ float g_psum[H * NB * 2 * 64];         // split-K partial row sums
__device__ __half g_qh[H * L * D];   // fp16(q)
__device__ __half g_qf[H * L * D];   // softmax(q) fp16
__device__ __half g_kh[H * L * D];   // fp16(k)
__device__ __half g_vt[H * L * D];   // V^T per block: [h][blk][dim][key]
__device__ __half g_kft[H * L * D];  // softmax(k)^T per block

// ---------------- PTX helpers ----------------
__device__ __forceinline__ void cp16(uint32_t dst, const void* src) {
    asm volatile("cp.async.cg.shared.global [%0], [%1], 16;" :: "r"(dst), "l"(src));
}
__device__ __forceinline__ void cp_commit() { asm volatile("cp.async.commit_group;"); }
__device__ __forceinline__ void cp_wait0() { asm volatile("cp.async.wait_group 0;"); }

__device__ __forceinline__ void ldsm4(uint32_t a, uint32_t& r0, uint32_t& r1,
                                      uint32_t& r2, uint32_t& r3) {
    asm volatile("ldmatrix.sync.aligned.m8n8.x4.shared.b16 {%0,%1,%2,%3}, [%4];"
                 : "=r"(r0), "=r"(r1), "=r"(r2), "=r"(r3) : "r"(a));
}
__device__ __forceinline__ void mma_f16(float* d, const uint32_t* a, const uint32_t* b) {
    asm volatile("mma.sync.aligned.m16n8k16.row.col.f32.f16.f16.f32 "
                 "{%0,%1,%2,%3}, {%4,%5,%6,%7}, {%8,%9}, {%0,%1,%2,%3};"
                 : "+f"(d[0]), "+f"(d[1]), "+f"(d[2]), "+f"(d[3])
                 : "r"(a[0]), "r"(a[1]), "r"(a[2]), "r"(a[3]), "r"(b[0]), "r"(b[1]));
}
__device__ __forceinline__ uint32_t pack_h2(float hi, float lo) {
    uint32_t d;
    asm("cvt.rn.f16x2.f32 %0, %1, %2;" : "=r"(d) : "f"(hi), "f"(lo));
    return d;
}

// ---------------- prep: fp16 casts, vt/kft, qf, block means, ksum partials ----------------
__global__ __launch_bounds__(256)
void prep_kernel(const float* __restrict__ q, const float* __restrict__ k,
                 const float* __restrict__ v) {
    __shared__ float vt[64][65];
    __shared__ float kt[64][65];
    __shared__ float psq[8][64], psk[8][64];
    int b = blockIdx.x, t = threadIdx.x, w = t >> 5, lane = t & 31;
    size_t base = (size_t)b * 4096;
    int c0 = (t & 31) * 2;
    int rgrp = t >> 5;
    float sq0 = 0.f, sq1 = 0.f, sk0 = 0.f, sk1 = 0.f;
#pragma unroll
    for (int m = 0; m < 8; m++) {
        int i2 = t + 256 * m;
        int i = i2 * 2;
        int row = i2 >> 5;
        float2 xq = *(const float2*)&q[base + i];
        *(uint32_t*)&g_qh[base + i] = pack_h2(xq.y, xq.x);
        sq0 += xq.x; sq1 += xq.y;
        float2 xk = *(const float2*)&k[base + i];
        *(uint32_t*)&g_kh[base + i] = pack_h2(xk.y, xk.x);
        sk0 += xk.x; sk1 += xk.y;
        float2 xv = *(const float2*)&v[base + i];
        vt[c0][row] = xv.x; vt[c0 + 1][row] = xv.y;
    }
    psq[rgrp][c0] = sq0; psq[rgrp][c0 + 1] = sq1;
    psk[rgrp][c0] = sk0; psk[rgrp][c0 + 1] = sk1;
    // k softmax per key row -> kt[dim][key] (transposed)
#pragma unroll
    for (int r8 = 0; r8 < 8; r8++) {
        int row = w * 8 + r8;
        float x0 = k[base + row * 64 + lane], x1 = k[base + row * 64 + lane + 32];
        float mx = fmaxf(x0, x1);
#pragma unroll
        for (int o = 16; o >= 1; o >>= 1) mx = fmaxf(mx, __shfl_xor_sync(~0u, mx, o));
        float p0 = __expf(x0 - mx), p1 = __expf(x1 - mx);
        float sum = p0 + p1;
#pragma unroll
        for (int o = 16; o >= 1; o >>= 1) sum += __shfl_xor_sync(~0u, sum, o);
        float inv = 1.f / sum;
        kt[lane][row] = p0 * inv;
        kt[lane + 32][row] = p1 * inv;
    }
    // q softmax per row -> g_qf fp16
#pragma unroll
    for (int r8 = 0; r8 < 8; r8++) {
        int row = w * 8 + r8;
        float x0 = q[base + row * 64 + lane], x1 = q[base + row * 64 + lane + 32];
        float mx = fmaxf(x0, x1);
#pragma unroll
        for (int o = 16; o >= 1; o >>= 1) mx = fmaxf(mx, __shfl_xor_sync(~0u, mx, o));
        float p0 = __expf(x0 - mx), p1 = __expf(x1 - mx);
        float sum = p0 + p1;
#pragma unroll
        for (int o = 16; o >= 1; o >>= 1) sum += __shfl_xor_sync(~0u, sum, o);
        float inv = 1.f / sum;
        g_qf[base + row * 64 + lane] = __float2half(p0 * inv);
        g_qf[base + row * 64 + lane + 32] = __float2half(p1 * inv);
    }
    __syncthreads();
    if (t < 64) {
        float a = 0.f, c = 0.f;
#pragma unroll
        for (int g = 0; g < 8; g++) { a += psq[g][t]; c += psk[g][t]; }
        g_pq[b * 64 + t] = a * (1.f / 64.f);
        g_pk[b * 64 + t] = c * (1.f / 64.f);
        float s = 0.f;
#pragma unroll
        for (int key = 0; key < 64; key++) s += kt[t][key];
        g_ksum_part[b * 64 + t] = s;
    }
#pragma unroll
    for (int m = 0; m < 8; m++) {
        int i2 = t + 256 * m;
        int i = i2 * 2;
        int dim = i2 >> 5, k0 = (i2 & 31) * 2;
        *(uint32_t*)&g_vt[base + i] = pack_h2(vt[dim][k0 + 1], vt[dim][k0]);
        *(uint32_t*)&g_kft[base + i] = pack_h2(kt[dim][k0 + 1], kt[dim][k0]);
    }
}

// ---------------- kv partials = kf^T v (fp16 mma, per-CTA partial) ----------------
#define KV_BUF 16384
__global__ __launch_bounds__(128)
void kvacc_mma_kernel() {
    __shared__ __align__(16) char smk[2 * KV_BUF];
    uint32_t sb = (uint32_t)__cvta_generic_to_shared(smk);
    int t = threadIdx.x, w = t >> 5, lane = t & 31;
    int bid = blockIdx.x;
    const int nt = 64 / KVP;
    size_t tb0 = (size_t)bid * nt * 4096;

    uint32_t soff[4]; int goff[4];
#pragma unroll
    for (int i = 0; i < 4; i++) {
        int c = t + 128 * i;
        int row = c >> 3, c16 = c & 7;
        soff[i] = row * 128 + ((c16 ^ (row & 7)) << 4);
        goff[i] = c * 16;
    }
#pragma unroll
    for (int i = 0; i < 4; i++) {
        cp16(sb + soff[i], (const char*)(g_kft + tb0) + goff[i]);
        cp16(sb + 8192 + soff[i], (const char*)(g_vt + tb0) + goff[i]);
    }
    cp_commit(); cp_wait0();
    __syncthreads();

    float oacc[8][4];
#pragma unroll
    for (int n = 0; n < 8; n++)
#pragma unroll
        for (int e = 0; e < 4; e++) oacc[n][e] = 0.f;

    const uint32_t loff = (lane & 7) * 128;
    const uint32_t xt = (lane & 7) << 4;
    const uint32_t xh = (lane >> 3) * 16;

    for (int j = 0; j < nt; j++) {
        uint32_t cb = sb + ((j & 1) ? KV_BUF : 0);
        if (j + 1 < nt) {
            size_t tb = tb0 + (size_t)(j + 1) * 4096;
            uint32_t nb = sb + ((j & 1) ? 0 : KV_BUF);
#pragma unroll
            for (int i = 0; i < 4; i++) {
                cp16(nb + soff[i], (const char*)(g_kft + tb) + goff[i]);
                cp16(nb + 8192 + soff[i], (const char*)(g_vt + tb) + goff[i]);
            }
            cp_commit();
        }
        uint32_t af[4][4];
        {
            int r = 16 * w + (lane & 7) + 8 * ((lane >> 3) & 1);
            int ct = lane >> 4;
#pragma unroll
            for (int kc = 0; kc < 4; kc++) {
                uint32_t c16i = (uint32_t)(kc * 2 + ct);
                uint32_t a = cb + r * 128 + ((c16i ^ (r & 7)) << 4);
                ldsm4(a, af[kc][0], af[kc][1], af[kc][2], af[kc][3]);
            }
        }
        uint32_t vb = cb + 8192 + loff;
#pragma unroll
        for (int n = 0; n < 8; n++) {
            uint32_t vf[8];
            ldsm4(vb + n * 1024 + (xh ^ xt), vf[0], vf[1], vf[2], vf[3]);
            ldsm4(vb + n * 1024 + ((64 + xh) ^ xt), vf[4], vf[5], vf[6], vf[7]);
#pragma unroll
            for (int kc = 0; kc < 4; kc++)
                mma_f16(oacc[n], af[kc], &vf[2 * kc]);
        }
        if (j + 1 < nt) cp_wait0();
        __syncthreads();
    }

    int d0 = 16 * w + (lane >> 2), e0 = (lane & 3) * 2;
    float* kvp = g_kvp + (size_t)bid * 4096;
#pragma unroll
    for (int n = 0; n < 8; n++) {
        kvp[d0 * 64 + n * 8 + e0] = oacc[n][0];
        kvp[d0 * 64 + n * 8 + e0 + 1] = oacc[n][1];
        kvp[(d0 + 8) * 64 + n * 8 + e0] = oacc[n][2];
        kvp[(d0 + 8) * 64 + n * 8 + e0 + 1] = oacc[n][3];
    }
}

// ---------------- reduce kv partials + M = kv @ W^T ----------------
__global__ __launch_bounds__(512)
void kvmat_kernel(const float* __restrict__ W) {
    __shared__ float W_s[64 * 65];
    __shared__ float kv_s[8][64];
    int h = blockIdx.x >> 3, rb = blockIdx.x & 7;
    int t = threadIdx.x;
    int r = t >> 6, f = t & 63;
    for (int i = t; i < 4096; i += 512)
        W_s[(i >> 6) * 65 + (i & 63)] = W[i];
    {
        float s = 0.f;
        const float* p = g_kvp + (size_t)h * KVP * 4096 + (rb * 8 + r) * 64 + f;
#pragma unroll
        for (int c = 0; c < KVP; c++) s += p[(size_t)c * 4096];
        kv_s[r][f] = s;
    }
    if (rb == 0 && t < 64) {
        float s = 0.f;
#pragma unroll
        for (int blk = 0; blk < 64; blk++) s += g_ksum_part[(h * 64 + blk) * 64 + t];
        g_ksum[h * 64 + t] = s;
    }
    __syncthreads();
    float m = 0.f;
#pragma unroll
    for (int ff = 0; ff < 64; ff++) m += kv_s[r][ff] * W_s[f * 65 + ff];
    g_M[h * 4096 + (rb * 8 + r) * 64 + f] = m;
}

// ---------------- sparse attention: in-CTA topk + split-K halves ----------------
#define BUFSZ 16384
__global__ __launch_bounds__(128, 6)
void sparse_mma_kernel() {
    extern __shared__ char sm[];
    __shared__ float sc_s[64];
    __shared__ float pq_s[64];
    __shared__ int lut_s[8];
    uint32_t sb = (uint32_t)__cvta_generic_to_shared(sm);
    int t = threadIdx.x, w = t >> 5, lane = t & 31;
    int idx = blockIdx.x;
    int h = idx >> 7, qb = (idx >> 1) & 63;
    int lo = (idx & 1) * 8;

    // ---- in-CTA pooled-score topk (ranks lo..lo+7) ----
    if (t < 64) pq_s[t] = g_pq[(h * NB + qb) * 64 + t];
    __syncthreads();
    if (t < 64) {
        const float* pk = &g_pk[(h * NB + t) * 64];
        float s = 0.f;
#pragma unroll
        for (int d = 0; d < 64; d++) s += pq_s[d] * pk[d];
        sc_s[t] = s;
    }
    __syncthreads();
    if (t < 64) {
        float mysc = sc_s[t];
        int rank = 0;
#pragma unroll
        for (int j = 0; j < 64; j++) {
            float o = sc_s[j];
            rank += (o > mysc) || (o == mysc && j < t);
        }
        if (rank >= lo && rank < lo + 8) lut_s[rank - lo] = t;
    }

    // per-thread loader offsets
    uint32_t soff[4]; int goff[4];
#pragma unroll
    for (int i = 0; i < 4; i++) {
        int c = t + 128 * i;
        int row = c >> 3, c16 = c & 7;
        soff[i] = row * 128 + ((c16 ^ (row & 7)) << 4);
        goff[i] = c * 16;
    }
    // Q fragments
    uint32_t qhf[4][4];
    {
        size_t r0 = ((size_t)h * L + qb * 64 + w * 16 + (lane >> 2)) * 64 + (lane & 3) * 2;
#pragma unroll
        for (int c = 0; c < 4; c++) {
            qhf[c][0] = *(const uint32_t*)&g_qh[r0 + c * 16];
            qhf[c][1] = *(const uint32_t*)&g_qh[r0 + 512 + c * 16];
            qhf[c][2] = *(const uint32_t*)&g_qh[r0 + c * 16 + 8];
            qhf[c][3] = *(const uint32_t*)&g_qh[r0 + 512 + c * 16 + 8];
        }
    }
    __syncthreads();   // lut_s ready
    {
        size_t ko = ((size_t)h * L + (size_t)lut_s[0] * 64) * 64;
#pragma unroll
        for (int i = 0; i < 4; i++) {
            cp16(sb + soff[i], (const char*)(g_kh + ko) + goff[i]);
            cp16(sb + 8192 + soff[i], (const char*)(g_vt + ko) + goff[i]);
        }
    }
    cp_commit(); cp_wait0();
    __syncthreads();

    float oacc[8][4];
#pragma unroll
    for (int n = 0; n < 8; n++)
#pragma unroll
        for (int e = 0; e < 4; e++) oacc[n][e] = 0.f;
    float psum0 = 0.f, psum1 = 0.f;

    const uint32_t loff = (lane & 7) * 128;
    const uint32_t xt = (lane & 7) << 4;
    const uint32_t xh = (lane >> 3) * 16;

    for (int it = 0; it < 8; it++) {
        uint32_t cb = sb + ((it & 1) ? BUFSZ : 0);
        if (it + 1 < 8) {
            size_t ko = ((size_t)h * L + (size_t)lut_s[it + 1] * 64) * 64;
            uint32_t nb = sb + ((it & 1) ? 0 : BUFSZ);
#pragma unroll
            for (int i = 0; i < 4; i++) {
                cp16(nb + soff[i], (const char*)(g_kh + ko) + goff[i]);
                cp16(nb + 8192 + soff[i], (const char*)(g_vt + ko) + goff[i]);
            }
            cp_commit();
        }
        uint32_t pa[4][4];
#pragma unroll
        for (int kc = 0; kc < 4; kc++) {
#pragma unroll
            for (int jj = 0; jj < 2; jj++) {
                int j = 2 * kc + jj;
                float sa[4] = {0.f, 0.f, 0.f, 0.f};
                uint32_t ab = cb + j * 1024 + loff;
                uint32_t khf[8];
                ldsm4(ab + (xh ^ xt), khf[0], khf[1], khf[2], khf[3]);
                ldsm4(ab + ((64 + xh) ^ xt), khf[4], khf[5], khf[6], khf[7]);
#pragma unroll
                for (int c = 0; c < 4; c++)
                    mma_f16(sa, qhf[c], &khf[2 * c]);
                float p0 = __expf(sa[0] * 0.125f);
                float p1 = __expf(sa[1] * 0.125f);
                float p2 = __expf(sa[2] * 0.125f);
                float p3 = __expf(sa[3] * 0.125f);
                psum0 += p0 + p1; psum1 += p2 + p3;
                pa[kc][jj * 2] = pack_h2(p1, p0);
                pa[kc][jj * 2 + 1] = pack_h2(p3, p2);
            }
        }
        uint32_t vb = cb + 8192 + loff;
#pragma unroll
        for (int n = 0; n < 8; n++) {
            uint32_t vf[8];
            ldsm4(vb + n * 1024 + (xh ^ xt), vf[0], vf[1], vf[2], vf[3]);
            ldsm4(vb + n * 1024 + ((64 + xh) ^ xt), vf[4], vf[5], vf[6], vf[7]);
#pragma unroll
            for (int kc = 0; kc < 4; kc++)
                mma_f16(oacc[n], pa[kc], &vf[2 * kc]);
        }
        if (it + 1 < 8) cp_wait0();
        __syncthreads();
    }

    psum0 += __shfl_xor_sync(~0u, psum0, 1);
    psum0 += __shfl_xor_sync(~0u, psum0, 2);
    psum1 += __shfl_xor_sync(~0u, psum1, 1);
    psum1 += __shfl_xor_sync(~0u, psum1, 2);
    if ((lane & 3) == 0) {
        g_psum[idx * 64 + w * 16 + (lane >> 2)] = psum0;
        g_psum[idx * 64 + w * 16 + (lane >> 2) + 8] = psum1;
    }
    float inv0 = 1.f / psum0, inv1 = 1.f / psum1;
    __half* op = g_oparth + (size_t)idx * 4096 + (w * 16 + (lane >> 2)) * 64;
#pragma unroll
    for (int n = 0; n < 8; n++) {
        int c = n * 8 + (lane & 3) * 2;
        *(uint32_t*)(op + c) = pack_h2(oacc[n][1] * inv0, oacc[n][0] * inv0);
        *(uint32_t*)(op + 512 + c) = pack_h2(oacc[n][3] * inv1, oacc[n][2] * inv1);
    }
}

// ---------------- combine partials + linear branch (WRITES out) ----------------
__global__ __launch_bounds__(256)
void lin_out_kernel(const float* __restrict__ bias, float* __restrict__ out) {
    __shared__ float M_s[4096], ks_s[64], b_s[64];
    __shared__ float qf_s[8][64];
    int h = blockIdx.x >> 7, rb = blockIdx.x & 127;
    int t = threadIdx.x, w = t >> 5, lane = t & 31;
    for (int i = t; i < 4096; i += 256) M_s[i] = g_M[h * 4096 + i];
    if (t < 64) { ks_s[t] = g_ksum[h * 64 + t]; b_s[t] = bias[t]; }
    __syncthreads();
#pragma unroll
    for (int rr = 0; rr < 4; rr++) {
        int row = rb * 32 + w * 4 + rr;
        size_t grow = (size_t)h * L + row;
        int qb = row >> 6, rloc = row & 63;
        float qf0 = __half2float(g_qf[grow * 64 + lane]);
        float qf1 = __half2float(g_qf[grow * 64 + lane + 32]);
        float dn = qf0 * ks_s[lane] + qf1 * ks_s[lane + 32];
#pragma unroll
        for (int o = 16; o >= 1; o >>= 1) dn += __shfl_xor_sync(~0u, dn, o);
        dn += 1e-5f;
        qf_s[w][lane] = qf0; qf_s[w][lane + 32] = qf1;
        __syncwarp();
        float t0 = 0.f, t1 = 0.f;
#pragma unroll
        for (int dd = 0; dd < 64; dd++) {
            float qd = qf_s[w][dd];
            t0 += qd * M_s[dd * 64 + lane];
            t1 += qd * M_s[dd * 64 + lane + 32];
        }
        float invd = 1.f / dn;
        int pidx = (h * 64 + qb) * 2;
        size_t pb = (size_t)pidx * 4096 + rloc * 64;
        float sA = g_psum[pidx * 64 + rloc];
        float sB = g_psum[(pidx + 1) * 64 + rloc];
        float invs = 1.f / (sA + sB);
        float wA = sA * invs, wB = sB * invs;
        float s0 = __half2float(g_oparth[pb + lane]) * wA +
                   __half2float(g_oparth[pb + 4096 + lane]) * wB;
        float s1 = __half2float(g_oparth[pb + lane + 32]) * wA +
                   __half2float(g_oparth[pb + 4096 + lane + 32]) * wB;
        out[grow * 64 + lane] = s0 + t0 * invd + b_s[lane];
        out[grow * 64 + lane + 32] = s1 + t1 * invd + b_s[lane + 32];
    }
}

// ---------------- launch ----------------
extern "C" void kernel_launch(void* const* d_in, const int* in_sizes, int n_in,
                              void* d_out, int out_size) {
    const float* q = (const float*)d_in[0];
    const float* k = (const float*)d_in[1];
    const float* v = (const float*)d_in[2];
    const float* W = (const float*)d_in[3];
    const float* b = (const float*)d_in[4];
    float* out = (float*)d_out;

    prep_kernel<<<H * NB, 256>>>(q, k, v);        // 0
    kvacc_mma_kernel<<<H * KVP, 128>>>();         // 1
    kvmat_kernel<<<H * 8, 512>>>(W);              // 2
    cudaFuncSetAttribute(sparse_mma_kernel,
                         cudaFuncAttributeMaxDynamicSharedMemorySize, 2 * BUFSZ);
    sparse_mma_kernel<<<H * NB * 2, 128, 2 * BUFSZ>>>();   // 3 (profiled slot)
    lin_out_kernel<<<H * 128, 256>>>(b, out);     // 4
}

// round 16
// speedup vs baseline: 1.0580x; 1.0580x over previous
#include <cuda_runtime.h>
#include <cuda_bf16.h>
#include <cuda_fp16.h>
#include <cstdint>

#define H 8
#define L 4096
#define D 64
#define NB 64
#define TOPK 16
#define NEG_BIG (-1e30f)
#define KVP 16   // kv partials per head

// ---------------- scratch ----------------
__device__ float g_pq[H * NB * D];
__device__ float g_pk[H * NB * D];
__device__ int   g_lut[H * NB * TOPK];
__device__ float g_kvp[H * KVP * D * D];
__device__ float g_M[H * D * D];
__device__ float g_ksum[H * D];
__device__ float g_ksum_part[H * NB * D];
__device__ __half g_oparth[H * NB * 2 * 64 * D];  // split-K partial O (normalized, fp16)
__device__ float g_psum[H * NB * 2 * 64];         // split-K partial row sums
__device__ __half g_qh[H * L * D];   // fp16(q)
__device__ __half g_qf[H * L * D];   // softmax(q) fp16
__device__ __half g_kh[H * L * D];   // fp16(k)
__device__ __half g_vt[H * L * D];   // V^T per block: [h][blk][dim][key]
__device__ __half g_kft[H * L * D];  // softmax(k)^T per block

// ---------------- PTX helpers ----------------
__device__ __forceinline__ void cp16(uint32_t dst, const void* src) {
    asm volatile("cp.async.cg.shared.global [%0], [%1], 16;" :: "r"(dst), "l"(src));
}
__device__ __forceinline__ void cp_commit() { asm volatile("cp.async.commit_group;"); }
__device__ __forceinline__ void cp_wait0() { asm volatile("cp.async.wait_group 0;"); }

__device__ __forceinline__ void ldsm4(uint32_t a, uint32_t& r0, uint32_t& r1,
                                      uint32_t& r2, uint32_t& r3) {
    asm volatile("ldmatrix.sync.aligned.m8n8.x4.shared.b16 {%0,%1,%2,%3}, [%4];"
                 : "=r"(r0), "=r"(r1), "=r"(r2), "=r"(r3) : "r"(a));
}
__device__ __forceinline__ void mma_f16(float* d, const uint32_t* a, const uint32_t* b) {
    asm volatile("mma.sync.aligned.m16n8k16.row.col.f32.f16.f16.f32 "
                 "{%0,%1,%2,%3}, {%4,%5,%6,%7}, {%8,%9}, {%0,%1,%2,%3};"
                 : "+f"(d[0]), "+f"(d[1]), "+f"(d[2]), "+f"(d[3])
                 : "r"(a[0]), "r"(a[1]), "r"(a[2]), "r"(a[3]), "r"(b[0]), "r"(b[1]));
}
__device__ __forceinline__ uint32_t pack_h2(float hi, float lo) {
    uint32_t d;
    asm("cvt.rn.f16x2.f32 %0, %1, %2;" : "=r"(d) : "f"(hi), "f"(lo));
    return d;
}

// ---------------- prep: fp16 casts, vt/kft, qf, block means, ksum partials ----------------
__global__ __launch_bounds__(256)
void prep_kernel(const float* __restrict__ q, const float* __restrict__ k,
                 const float* __restrict__ v) {
    __shared__ float vt[64][65];
    __shared__ float kt[64][65];
    __shared__ float psq[8][64], psk[8][64];
    int b = blockIdx.x, t = threadIdx.x, w = t >> 5, lane = t & 31;
    size_t base = (size_t)b * 4096;
    int c0 = (t & 31) * 2;
    int rgrp = t >> 5;
    float sq0 = 0.f, sq1 = 0.f, sk0 = 0.f, sk1 = 0.f;
#pragma unroll
    for (int m = 0; m < 8; m++) {
        int i2 = t + 256 * m;
        int i = i2 * 2;
        int row = i2 >> 5;
        float2 xq = *(const float2*)&q[base + i];
        *(uint32_t*)&g_qh[base + i] = pack_h2(xq.y, xq.x);
        sq0 += xq.x; sq1 += xq.y;
        float2 xk = *(const float2*)&k[base + i];
        *(uint32_t*)&g_kh[base + i] = pack_h2(xk.y, xk.x);
        sk0 += xk.x; sk1 += xk.y;
        float2 xv = *(const float2*)&v[base + i];
        vt[c0][row] = xv.x; vt[c0 + 1][row] = xv.y;
    }
    psq[rgrp][c0] = sq0; psq[rgrp][c0 + 1] = sq1;
    psk[rgrp][c0] = sk0; psk[rgrp][c0 + 1] = sk1;
    // k softmax per key row -> kt[dim][key] (transposed)
#pragma unroll
    for (int r8 = 0; r8 < 8; r8++) {
        int row = w * 8 + r8;
        float x0 = k[base + row * 64 + lane], x1 = k[base + row * 64 + lane + 32];
        float mx = fmaxf(x0, x1);
#pragma unroll
        for (int o = 16; o >= 1; o >>= 1) mx = fmaxf(mx, __shfl_xor_sync(~0u, mx, o));
        float p0 = __expf(x0 - mx), p1 = __expf(x1 - mx);
        float sum = p0 + p1;
#pragma unroll
        for (int o = 16; o >= 1; o >>= 1) sum += __shfl_xor_sync(~0u, sum, o);
        float inv = 1.f / sum;
        kt[lane][row] = p0 * inv;
        kt[lane + 32][row] = p1 * inv;
    }
    // q softmax per row -> g_qf fp16
#pragma unroll
    for (int r8 = 0; r8 < 8; r8++) {
        int row = w * 8 + r8;
        float x0 = q[base + row * 64 + lane], x1 = q[base + row * 64 + lane + 32];
        float mx = fmaxf(x0, x1);
#pragma unroll
        for (int o = 16; o >= 1; o >>= 1) mx = fmaxf(mx, __shfl_xor_sync(~0u, mx, o));
        float p0 = __expf(x0 - mx), p1 = __expf(x1 - mx);
        float sum = p0 + p1;
#pragma unroll
        for (int o = 16; o >= 1; o >>= 1) sum += __shfl_xor_sync(~0u, sum, o);
        float inv = 1.f / sum;
        g_qf[base + row * 64 + lane] = __float2half(p0 * inv);
        g_qf[base + row * 64 + lane + 32] = __float2half(p1 * inv);
    }
    __syncthreads();
    if (t < 64) {
        float a = 0.f, c = 0.f;
#pragma unroll
        for (int g = 0; g < 8; g++) { a += psq[g][t]; c += psk[g][t]; }
        g_pq[b * 64 + t] = a * (1.f / 64.f);
        g_pk[b * 64 + t] = c * (1.f / 64.f);
        float s = 0.f;
#pragma unroll
        for (int key = 0; key < 64; key++) s += kt[t][key];
        g_ksum_part[b * 64 + t] = s;
    }
#pragma unroll
    for (int m = 0; m < 8; m++) {
        int i2 = t + 256 * m;
        int i = i2 * 2;
        int dim = i2 >> 5, k0 = (i2 & 31) * 2;
        *(uint32_t*)&g_vt[base + i] = pack_h2(vt[dim][k0 + 1], vt[dim][k0]);
        *(uint32_t*)&g_kft[base + i] = pack_h2(kt[dim][k0 + 1], kt[dim][k0]);
    }
}

// ---------------- topk (parallel rank selection; coalesced) ----------------
__global__ void topk_kernel() {
    __shared__ float sc[64], pqs[64];
    int h = blockIdx.x >> 6, qb = blockIdx.x & 63, t = threadIdx.x;
    pqs[t] = g_pq[(h * NB + qb) * D + t];
    __syncthreads();
    const float* pk = &g_pk[(h * NB + t) * D];
    float s = 0.f;
#pragma unroll
    for (int d = 0; d < 64; d++) s += pqs[d] * pk[d];
    sc[t] = s;
    __syncthreads();
    float mysc = sc[t];
    int rank = 0;
#pragma unroll
    for (int j = 0; j < 64; j++) {
        float o = sc[j];
        rank += (o > mysc) || (o == mysc && j < t);
    }
    if (rank < TOPK) g_lut[(h * NB + qb) * TOPK + rank] = t;
}

// ---------------- kv partials = kf^T v (fp16 mma, per-CTA partial) ----------------
#define KV_BUF 16384
__global__ __launch_bounds__(128)
void kvacc_mma_kernel() {
    __shared__ __align__(16) char smk[2 * KV_BUF];
    uint32_t sb = (uint32_t)__cvta_generic_to_shared(smk);
    int t = threadIdx.x, w = t >> 5, lane = t & 31;
    int bid = blockIdx.x;
    const int nt = 64 / KVP;
    size_t tb0 = (size_t)bid * nt * 4096;

    uint32_t soff[4]; int goff[4];
#pragma unroll
    for (int i = 0; i < 4; i++) {
        int c = t + 128 * i;
        int row = c >> 3, c16 = c & 7;
        soff[i] = row * 128 + ((c16 ^ (row & 7)) << 4);
        goff[i] = c * 16;
    }
#pragma unroll
    for (int i = 0; i < 4; i++) {
        cp16(sb + soff[i], (const char*)(g_kft + tb0) + goff[i]);
        cp16(sb + 8192 + soff[i], (const char*)(g_vt + tb0) + goff[i]);
    }
    cp_commit(); cp_wait0();
    __syncthreads();

    float oacc[8][4];
#pragma unroll
    for (int n = 0; n < 8; n++)
#pragma unroll
        for (int e = 0; e < 4; e++) oacc[n][e] = 0.f;

    const uint32_t loff = (lane & 7) * 128;
    const uint32_t xt = (lane & 7) << 4;
    const uint32_t xh = (lane >> 3) * 16;

    for (int j = 0; j < nt; j++) {
        uint32_t cb = sb + ((j & 1) ? KV_BUF : 0);
        if (j + 1 < nt) {
            size_t tb = tb0 + (size_t)(j + 1) * 4096;
            uint32_t nb = sb + ((j & 1) ? 0 : KV_BUF);
#pragma unroll
            for (int i = 0; i < 4; i++) {
                cp16(nb + soff[i], (const char*)(g_kft + tb) + goff[i]);
                cp16(nb + 8192 + soff[i], (const char*)(g_vt + tb) + goff[i]);
            }
            cp_commit();
        }
        uint32_t af[4][4];
        {
            int r = 16 * w + (lane & 7) + 8 * ((lane >> 3) & 1);
            int ct = lane >> 4;
#pragma unroll
            for (int kc = 0; kc < 4; kc++) {
                uint32_t c16i = (uint32_t)(kc * 2 + ct);
                uint32_t a = cb + r * 128 + ((c16i ^ (r & 7)) << 4);
                ldsm4(a, af[kc][0], af[kc][1], af[kc][2], af[kc][3]);
            }
        }
        uint32_t vb = cb + 8192 + loff;
#pragma unroll
        for (int n = 0; n < 8; n++) {
            uint32_t vf[8];
            ldsm4(vb + n * 1024 + (xh ^ xt), vf[0], vf[1], vf[2], vf[3]);
            ldsm4(vb + n * 1024 + ((64 + xh) ^ xt), vf[4], vf[5], vf[6], vf[7]);
#pragma unroll
            for (int kc = 0; kc < 4; kc++)
                mma_f16(oacc[n], af[kc], &vf[2 * kc]);
        }
        if (j + 1 < nt) cp_wait0();
        __syncthreads();
    }

    int d0 = 16 * w + (lane >> 2), e0 = (lane & 3) * 2;
    float* kvp = g_kvp + (size_t)bid * 4096;
#pragma unroll
    for (int n = 0; n < 8; n++) {
        kvp[d0 * 64 + n * 8 + e0] = oacc[n][0];
        kvp[d0 * 64 + n * 8 + e0 + 1] = oacc[n][1];
        kvp[(d0 + 8) * 64 + n * 8 + e0] = oacc[n][2];
        kvp[(d0 + 8) * 64 + n * 8 + e0 + 1] = oacc[n][3];
    }
}

// ---------------- reduce kv partials + M = kv @ W^T ----------------
__global__ __launch_bounds__(512)
void kvmat_kernel(const float* __restrict__ W) {
    __shared__ float W_s[64 * 65];
    __shared__ float kv_s[8][64];
    int h = blockIdx.x >> 3, rb = blockIdx.x & 7;
    int t = threadIdx.x;
    int r = t >> 6, f = t & 63;
    for (int i = t; i < 4096; i += 512)
        W_s[(i >> 6) * 65 + (i & 63)] = W[i];
    {
        float s = 0.f;
        const float* p = g_kvp + (size_t)h * KVP * 4096 + (rb * 8 + r) * 64 + f;
#pragma unroll
        for (int c = 0; c < KVP; c++) s += p[(size_t)c * 4096];
        kv_s[r][f] = s;
    }
    if (rb == 0 && t < 64) {
        float s = 0.f;
#pragma unroll
        for (int blk = 0; blk < 64; blk++) s += g_ksum_part[(h * 64 + blk) * 64 + t];
        g_ksum[h * 64 + t] = s;
    }
    __syncthreads();
    float m = 0.f;
#pragma unroll
    for (int ff = 0; ff < 64; ff++) m += kv_s[r][ff] * W_s[f * 65 + ff];
    g_M[h * 4096 + (rb * 8 + r) * 64 + f] = m;
}

// ---------------- sparse attention, split-K halves (normalized fp16 partials) ----------------
#define BUFSZ 16384
__global__ __launch_bounds__(128, 6)
void sparse_mma_kernel() {
    extern __shared__ char sm[];
    uint32_t sb = (uint32_t)__cvta_generic_to_shared(sm);
    int t = threadIdx.x, w = t >> 5, lane = t & 31;
    int idx = blockIdx.x;
    int h = idx >> 7, qb = (idx >> 1) & 63;
    const int* lut = &g_lut[(h * NB + qb) * TOPK + (idx & 1) * 8];

    uint32_t soff[4]; int goff[4];
#pragma unroll
    for (int i = 0; i < 4; i++) {
        int c = t + 128 * i;
        int row = c >> 3, c16 = c & 7;
        soff[i] = row * 128 + ((c16 ^ (row & 7)) << 4);
        goff[i] = c * 16;
    }
    uint32_t qhf[4][4];
    {
        size_t r0 = ((size_t)h * L + qb * 64 + w * 16 + (lane >> 2)) * 64 + (lane & 3) * 2;
#pragma unroll
        for (int c = 0; c < 4; c++) {
            qhf[c][0] = *(const uint32_t*)&g_qh[r0 + c * 16];
            qhf[c][1] = *(const uint32_t*)&g_qh[r0 + 512 + c * 16];
            qhf[c][2] = *(const uint32_t*)&g_qh[r0 + c * 16 + 8];
            qhf[c][3] = *(const uint32_t*)&g_qh[r0 + 512 + c * 16 + 8];
        }
    }
    {
        size_t ko = ((size_t)h * L + (size_t)lut[0] * 64) * 64;
#pragma unroll
        for (int i = 0; i < 4; i++) {
            cp16(sb + soff[i], (const char*)(g_kh + ko) + goff[i]);
            cp16(sb + 8192 + soff[i], (const char*)(g_vt + ko) + goff[i]);
        }
    }
    cp_commit(); cp_wait0();
    __syncthreads();

    float oacc[8][4];
#pragma unroll
    for (int n = 0; n < 8; n++)
#pragma unroll
        for (int e = 0; e < 4; e++) oacc[n][e] = 0.f;
    float psum0 = 0.f, psum1 = 0.f;

    const uint32_t loff = (lane & 7) * 128;
    const uint32_t xt = (lane & 7) << 4;
    const uint32_t xh = (lane >> 3) * 16;

    for (int it = 0; it < 8; it++) {
        uint32_t cb = sb + ((it & 1) ? BUFSZ : 0);
        if (it + 1 < 8) {
            size_t ko = ((size_t)h * L + (size_t)lut[it + 1] * 64) * 64;
            uint32_t nb = sb + ((it & 1) ? 0 : BUFSZ);
#pragma unroll
            for (int i = 0; i < 4; i++) {
                cp16(nb + soff[i], (const char*)(g_kh + ko) + goff[i]);
                cp16(nb + 8192 + soff[i], (const char*)(g_vt + ko) + goff[i]);
            }
            cp_commit();
        }
        uint32_t pa[4][4];
#pragma unroll
        for (int kc = 0; kc < 4; kc++) {
#pragma unroll
            for (int jj = 0; jj < 2; jj++) {
                int j = 2 * kc + jj;
                float sa[4] = {0.f, 0.f, 0.f, 0.f};
                uint32_t ab = cb + j * 1024 + loff;
                uint32_t khf[8];
                ldsm4(ab + (xh ^ xt), khf[0], khf[1], khf[2], khf[3]);
                ldsm4(ab + ((64 + xh) ^ xt), khf[4], khf[5], khf[6], khf[7]);
#pragma unroll
                for (int c = 0; c < 4; c++)
                    mma_f16(sa, qhf[c], &khf[2 * c]);
                float p0 = __expf(sa[0] * 0.125f);
                float p1 = __expf(sa[1] * 0.125f);
                float p2 = __expf(sa[2] * 0.125f);
                float p3 = __expf(sa[3] * 0.125f);
                psum0 += p0 + p1; psum1 += p2 + p3;
                pa[kc][jj * 2] = pack_h2(p1, p0);
                pa[kc][jj * 2 + 1] = pack_h2(p3, p2);
            }
        }
        uint32_t vb = cb + 8192 + loff;
#pragma unroll
        for (int n = 0; n < 8; n++) {
            uint32_t vf[8];
            ldsm4(vb + n * 1024 + (xh ^ xt), vf[0], vf[1], vf[2], vf[3]);
            ldsm4(vb + n * 1024 + ((64 + xh) ^ xt), vf[4], vf[5], vf[6], vf[7]);
#pragma unroll
            for (int kc = 0; kc < 4; kc++)
                mma_f16(oacc[n], pa[kc], &vf[2 * kc]);
        }
        if (it + 1 < 8) cp_wait0();
        __syncthreads();
    }

    psum0 += __shfl_xor_sync(~0u, psum0, 1);
    psum0 += __shfl_xor_sync(~0u, psum0, 2);
    psum1 += __shfl_xor_sync(~0u, psum1, 1);
    psum1 += __shfl_xor_sync(~0u, psum1, 2);
    if ((lane & 3) == 0) {
        g_psum[idx * 64 + w * 16 + (lane >> 2)] = psum0;
        g_psum[idx * 64 + w * 16 + (lane >> 2) + 8] = psum1;
    }
    float inv0 = 1.f / psum0, inv1 = 1.f / psum1;
    __half* op = g_oparth + (size_t)idx * 4096 + (w * 16 + (lane >> 2)) * 64;
#pragma unroll
    for (int n = 0; n < 8; n++) {
        int c = n * 8 + (lane & 3) * 2;
        *(uint32_t*)(op + c) = pack_h2(oacc[n][1] * inv0, oacc[n][0] * inv0);
        *(uint32_t*)(op + 512 + c) = pack_h2(oacc[n][3] * inv1, oacc[n][2] * inv1);
    }
}

// ---------------- combine partials + linear branch (WRITES out) ----------------
__global__ __launch_bounds__(256)
void lin_out_kernel(const float* __restrict__ bias, float* __restrict__ out) {
    __shared__ float M_s[4096], ks_s[64], b_s[64];
    __shared__ float qf_s[8][64];
    int h = blockIdx.x >> 7, rb = blockIdx.x & 127;
    int t = threadIdx.x, w = t >> 5, lane = t & 31;
    for (int i = t; i < 4096; i += 256) M_s[i] = g_M[h * 4096 + i];
    if (t < 64) { ks_s[t] = g_ksum[h * 64 + t]; b_s[t] = bias[t]; }
    __syncthreads();
#pragma unroll
    for (int rr = 0; rr < 4; rr++) {
        int row = rb * 32 + w * 4 + rr;
        size_t grow = (size_t)h * L + row;
        int qb = row >> 6, rloc = row & 63;
        float qf0 = __half2float(g_qf[grow * 64 + lane]);
        float qf1 = __half2float(g_qf[grow * 64 + lane + 32]);
        float dn = qf0 * ks_s[lane] + qf1 * ks_s[lane + 32];
#pragma unroll
        for (int o = 16; o >= 1; o >>= 1) dn += __shfl_xor_sync(~0u, dn, o);
        dn += 1e-5f;
        qf_s[w][lane] = qf0; qf_s[w][lane + 32] = qf1;
        __syncwarp();
        float t0 = 0.f, t1 = 0.f;
#pragma unroll
        for (int dd = 0; dd < 64; dd++) {
            float qd = qf_s[w][dd];
            t0 += qd * M_s[dd * 64 + lane];
            t1 += qd * M_s[dd * 64 + lane + 32];
        }
        float invd = 1.f / dn;
        int pidx = (h * 64 + qb) * 2;
        size_t pb = (size_t)pidx * 4096 + rloc * 64;
        float sA = g_psum[pidx * 64 + rloc];
        float sB = g_psum[(pidx + 1) * 64 + rloc];
        float invs = 1.f / (sA + sB);
        float wA = sA * invs, wB = sB * invs;
        float s0 = __half2float(g_oparth[pb + lane]) * wA +
                   __half2float(g_oparth[pb + 4096 + lane]) * wB;
        float s1 = __half2float(g_oparth[pb + lane + 32]) * wA +
                   __half2float(g_oparth[pb + 4096 + lane + 32]) * wB;
        out[grow * 64 + lane] = s0 + t0 * invd + b_s[lane];
        out[grow * 64 + lane + 32] = s1 + t1 * invd + b_s[lane + 32];
    }
}

// ---------------- launch ----------------
extern "C" void kernel_launch(void* const* d_in, const int* in_sizes, int n_in,
                              void* d_out, int out_size) {
    const float* q = (const float*)d_in[0];
    const float* k = (const float*)d_in[1];
    const float* v = (const float*)d_in[2];
    const float* W = (const float*)d_in[3];
    const float* b = (const float*)d_in[4];
    float* out = (float*)d_out;

    prep_kernel<<<H * NB, 256>>>(q, k, v);        // 0
    topk_kernel<<<H * NB, 64>>>();                // 1
    kvacc_mma_kernel<<<H * KVP, 128>>>();         // 2
    cudaFuncSetAttribute(sparse_mma_kernel,
                         cudaFuncAttributeMaxDynamicSharedMemorySize, 2 * BUFSZ);
    sparse_mma_kernel<<<H * NB * 2, 128, 2 * BUFSZ>>>();   // 3 (profiled slot)
    kvmat_kernel<<<H * 8, 512>>>(W);              // 4
    lin_out_kernel<<<H * 128, 256>>>(b, out);     // 5
}

// round 17
// speedup vs baseline: 1.0809x; 1.0217x over previous
#include <cuda_runtime.h>
#include <cuda_bf16.h>
#include <cuda_fp16.h>
#include <cstdint>

#define H 8
#define L 4096
#define D 64
#define NB 64
#define TOPK 16
#define NEG_BIG (-1e30f)
#define KVP 16   // kv partials per head

// ---------------- scratch ----------------
__device__ float g_pq[H * NB * D];
__device__ float g_pk[H * NB * D];
__device__ int   g_lut[H * NB * TOPK];
__device__ float g_kvp[H * KVP * D * D];
__device__ float g_M[H * D * D];
__device__ float g_ksum[H * D];
__device__ float g_ksum_part[H * NB * D];
__device__ __half g_oparth[H * NB * 2 * 64 * D];  // split-K partial O (normalized, fp16)
__device__ float g_psum[H * NB * 2 * 64];         // split-K partial row sums
__device__ __half g_qh[H * L * D];   // fp16(q)
__device__ __half g_qf[H * L * D];   // softmax(q) fp16
__device__ __half g_kh[H * L * D];   // fp16(k)
__device__ __half g_vt[H * L * D];   // V^T per block: [h][blk][dim][key]
__device__ __half g_kft[H * L * D];  // softmax(k)^T per block

// ---------------- PTX helpers ----------------
__device__ __forceinline__ void cp16(uint32_t dst, const void* src) {
    asm volatile("cp.async.cg.shared.global [%0], [%1], 16;" :: "r"(dst), "l"(src));
}
__device__ __forceinline__ void cp_commit() { asm volatile("cp.async.commit_group;"); }
__device__ __forceinline__ void cp_wait0() { asm volatile("cp.async.wait_group 0;"); }

__device__ __forceinline__ void ldsm4(uint32_t a, uint32_t& r0, uint32_t& r1,
                                      uint32_t& r2, uint32_t& r3) {
    asm volatile("ldmatrix.sync.aligned.m8n8.x4.shared.b16 {%0,%1,%2,%3}, [%4];"
                 : "=r"(r0), "=r"(r1), "=r"(r2), "=r"(r3) : "r"(a));
}
__device__ __forceinline__ void mma_f16(float* d, const uint32_t* a, const uint32_t* b) {
    asm volatile("mma.sync.aligned.m16n8k16.row.col.f32.f16.f16.f32 "
                 "{%0,%1,%2,%3}, {%4,%5,%6,%7}, {%8,%9}, {%0,%1,%2,%3};"
                 : "+f"(d[0]), "+f"(d[1]), "+f"(d[2]), "+f"(d[3])
                 : "r"(a[0]), "r"(a[1]), "r"(a[2]), "r"(a[3]), "r"(b[0]), "r"(b[1]));
}
__device__ __forceinline__ uint32_t pack_h2(float hi, float lo) {
    uint32_t d;
    asm("cvt.rn.f16x2.f32 %0, %1, %2;" : "=r"(d) : "f"(hi), "f"(lo));
    return d;
}

// ---------------- prep: single pass, in-register softmaxes ----------------
__global__ __launch_bounds__(256)
void prep_kernel(const float* __restrict__ q, const float* __restrict__ k,
                 const float* __restrict__ v) {
    __shared__ float vt[64][65];
    __shared__ float kt[64][65];
    __shared__ float psq[8][64], psk[8][64];
    int b = blockIdx.x, t = threadIdx.x, w = t >> 5, lane = t & 31;
    size_t base = (size_t)b * 4096;
    int col = lane * 2;
    float sq0 = 0.f, sq1 = 0.f, sk0 = 0.f, sk1 = 0.f;
#pragma unroll
    for (int m = 0; m < 8; m++) {
        int row = w + 8 * m;                 // warp holds the full row
        size_t ri = base + (size_t)row * 64 + col;
        // ---- q: cast + in-register row softmax ----
        float2 xq = *(const float2*)&q[ri];
        *(uint32_t*)&g_qh[ri] = pack_h2(xq.y, xq.x);
        sq0 += xq.x; sq1 += xq.y;
        float mq = fmaxf(xq.x, xq.y);
#pragma unroll
        for (int o = 16; o >= 1; o >>= 1) mq = fmaxf(mq, __shfl_xor_sync(~0u, mq, o));
        float eq0 = __expf(xq.x - mq), eq1 = __expf(xq.y - mq);
        float sqs = eq0 + eq1;
#pragma unroll
        for (int o = 16; o >= 1; o >>= 1) sqs += __shfl_xor_sync(~0u, sqs, o);
        float iq = 1.f / sqs;
        *(uint32_t*)&g_qf[ri] = pack_h2(eq1 * iq, eq0 * iq);
        // ---- k: cast + in-register row softmax -> kt transposed ----
        float2 xk = *(const float2*)&k[ri];
        *(uint32_t*)&g_kh[ri] = pack_h2(xk.y, xk.x);
        sk0 += xk.x; sk1 += xk.y;
        float mk = fmaxf(xk.x, xk.y);
#pragma unroll
        for (int o = 16; o >= 1; o >>= 1) mk = fmaxf(mk, __shfl_xor_sync(~0u, mk, o));
        float ek0 = __expf(xk.x - mk), ek1 = __expf(xk.y - mk);
        float sks = ek0 + ek1;
#pragma unroll
        for (int o = 16; o >= 1; o >>= 1) sks += __shfl_xor_sync(~0u, sks, o);
        float ik = 1.f / sks;
        kt[col][row] = ek0 * ik;
        kt[col + 1][row] = ek1 * ik;
        // ---- v: transpose into smem ----
        float2 xv = *(const float2*)&v[ri];
        vt[col][row] = xv.x; vt[col + 1][row] = xv.y;
    }
    psq[w][col] = sq0; psq[w][col + 1] = sq1;
    psk[w][col] = sk0; psk[w][col + 1] = sk1;
    __syncthreads();
    if (t < 64) {
        float a = 0.f, c = 0.f;
#pragma unroll
        for (int g = 0; g < 8; g++) { a += psq[g][t]; c += psk[g][t]; }
        g_pq[b * 64 + t] = a * (1.f / 64.f);
        g_pk[b * 64 + t] = c * (1.f / 64.f);
        float s = 0.f;
#pragma unroll
        for (int key = 0; key < 64; key++) s += kt[t][key];
        g_ksum_part[b * 64 + t] = s;
    }
#pragma unroll
    for (int m = 0; m < 8; m++) {
        int i2 = t + 256 * m;
        int i = i2 * 2;
        int dim = i2 >> 5, k0 = (i2 & 31) * 2;
        *(uint32_t*)&g_vt[base + i] = pack_h2(vt[dim][k0 + 1], vt[dim][k0]);
        *(uint32_t*)&g_kft[base + i] = pack_h2(kt[dim][k0 + 1], kt[dim][k0]);
    }
}

// ---------------- topk (parallel rank selection; coalesced) ----------------
__global__ void topk_kernel() {
    __shared__ float sc[64], pqs[64];
    int h = blockIdx.x >> 6, qb = blockIdx.x & 63, t = threadIdx.x;
    pqs[t] = g_pq[(h * NB + qb) * D + t];
    __syncthreads();
    const float* pk = &g_pk[(h * NB + t) * D];
    float s = 0.f;
#pragma unroll
    for (int d = 0; d < 64; d++) s += pqs[d] * pk[d];
    sc[t] = s;
    __syncthreads();
    float mysc = sc[t];
    int rank = 0;
#pragma unroll
    for (int j = 0; j < 64; j++) {
        float o = sc[j];
        rank += (o > mysc) || (o == mysc && j < t);
    }
    if (rank < TOPK) g_lut[(h * NB + qb) * TOPK + rank] = t;
}

// ---------------- kv partials = kf^T v (fp16 mma, per-CTA partial) ----------------
#define KV_BUF 16384
__global__ __launch_bounds__(128)
void kvacc_mma_kernel() {
    __shared__ __align__(16) char smk[2 * KV_BUF];
    uint32_t sb = (uint32_t)__cvta_generic_to_shared(smk);
    int t = threadIdx.x, w = t >> 5, lane = t & 31;
    int bid = blockIdx.x;
    const int nt = 64 / KVP;
    size_t tb0 = (size_t)bid * nt * 4096;

    uint32_t soff[4]; int goff[4];
#pragma unroll
    for (int i = 0; i < 4; i++) {
        int c = t + 128 * i;
        int row = c >> 3, c16 = c & 7;
        soff[i] = row * 128 + ((c16 ^ (row & 7)) << 4);
        goff[i] = c * 16;
    }
#pragma unroll
    for (int i = 0; i < 4; i++) {
        cp16(sb + soff[i], (const char*)(g_kft + tb0) + goff[i]);
        cp16(sb + 8192 + soff[i], (const char*)(g_vt + tb0) + goff[i]);
    }
    cp_commit(); cp_wait0();
    __syncthreads();

    float oacc[8][4];
#pragma unroll
    for (int n = 0; n < 8; n++)
#pragma unroll
        for (int e = 0; e < 4; e++) oacc[n][e] = 0.f;

    const uint32_t loff = (lane & 7) * 128;
    const uint32_t xt = (lane & 7) << 4;
    const uint32_t xh = (lane >> 3) * 16;

    for (int j = 0; j < nt; j++) {
        uint32_t cb = sb + ((j & 1) ? KV_BUF : 0);
        if (j + 1 < nt) {
            size_t tb = tb0 + (size_t)(j + 1) * 4096;
            uint32_t nb = sb + ((j & 1) ? 0 : KV_BUF);
#pragma unroll
            for (int i = 0; i < 4; i++) {
                cp16(nb + soff[i], (const char*)(g_kft + tb) + goff[i]);
                cp16(nb + 8192 + soff[i], (const char*)(g_vt + tb) + goff[i]);
            }
            cp_commit();
        }
        uint32_t af[4][4];
        {
            int r = 16 * w + (lane & 7) + 8 * ((lane >> 3) & 1);
            int ct = lane >> 4;
#pragma unroll
            for (int kc = 0; kc < 4; kc++) {
                uint32_t c16i = (uint32_t)(kc * 2 + ct);
                uint32_t a = cb + r * 128 + ((c16i ^ (r & 7)) << 4);
                ldsm4(a, af[kc][0], af[kc][1], af[kc][2], af[kc][3]);
            }
        }
        uint32_t vb = cb + 8192 + loff;
#pragma unroll
        for (int n = 0; n < 8; n++) {
            uint32_t vf[8];
            ldsm4(vb + n * 1024 + (xh ^ xt), vf[0], vf[1], vf[2], vf[3]);
            ldsm4(vb + n * 1024 + ((64 + xh) ^ xt), vf[4], vf[5], vf[6], vf[7]);
#pragma unroll
            for (int kc = 0; kc < 4; kc++)
                mma_f16(oacc[n], af[kc], &vf[2 * kc]);
        }
        if (j + 1 < nt) cp_wait0();
        __syncthreads();
    }

    int d0 = 16 * w + (lane >> 2), e0 = (lane & 3) * 2;
    float* kvp = g_kvp + (size_t)bid * 4096;
#pragma unroll
    for (int n = 0; n < 8; n++) {
        kvp[d0 * 64 + n * 8 + e0] = oacc[n][0];
        kvp[d0 * 64 + n * 8 + e0 + 1] = oacc[n][1];
        kvp[(d0 + 8) * 64 + n * 8 + e0] = oacc[n][2];
        kvp[(d0 + 8) * 64 + n * 8 + e0 + 1] = oacc[n][3];
    }
}

// ---------------- reduce kv partials + M = kv @ W^T ----------------
__global__ __launch_bounds__(512)
void kvmat_kernel(const float* __restrict__ W) {
    __shared__ float W_s[64 * 65];
    __shared__ float kv_s[8][64];
    int h = blockIdx.x >> 3, rb = blockIdx.x & 7;
    int t = threadIdx.x;
    int r = t >> 6, f = t & 63;
    for (int i = t; i < 4096; i += 512)
        W_s[(i >> 6) * 65 + (i & 63)] = W[i];
    {
        float s = 0.f;
        const float* p = g_kvp + (size_t)h * KVP * 4096 + (rb * 8 + r) * 64 + f;
#pragma unroll
        for (int c = 0; c < KVP; c++) s += p[(size_t)c * 4096];
        kv_s[r][f] = s;
    }
    if (rb == 0 && t < 64) {
        float s = 0.f;
#pragma unroll
        for (int blk = 0; blk < 64; blk++) s += g_ksum_part[(h * 64 + blk) * 64 + t];
        g_ksum[h * 64 + t] = s;
    }
    __syncthreads();
    float m = 0.f;
#pragma unroll
    for (int ff = 0; ff < 64; ff++) m += kv_s[r][ff] * W_s[f * 65 + ff];
    g_M[h * 4096 + (rb * 8 + r) * 64 + f] = m;
}

// ---------------- sparse attention, split-K halves (normalized fp16 partials) ----------------
#define BUFSZ 16384
__global__ __launch_bounds__(128, 6)
void sparse_mma_kernel() {
    extern __shared__ char sm[];
    uint32_t sb = (uint32_t)__cvta_generic_to_shared(sm);
    int t = threadIdx.x, w = t >> 5, lane = t & 31;
    int idx = blockIdx.x;
    int h = idx >> 7, qb = (idx >> 1) & 63;
    const int* lut = &g_lut[(h * NB + qb) * TOPK + (idx & 1) * 8];

    uint32_t soff[4]; int goff[4];
#pragma unroll
    for (int i = 0; i < 4; i++) {
        int c = t + 128 * i;
        int row = c >> 3, c16 = c & 7;
        soff[i] = row * 128 + ((c16 ^ (row & 7)) << 4);
        goff[i] = c * 16;
    }
    uint32_t qhf[4][4];
    {
        size_t r0 = ((size_t)h * L + qb * 64 + w * 16 + (lane >> 2)) * 64 + (lane & 3) * 2;
#pragma unroll
        for (int c = 0; c < 4; c++) {
            qhf[c][0] = *(const uint32_t*)&g_qh[r0 + c * 16];
            qhf[c][1] = *(const uint32_t*)&g_qh[r0 + 512 + c * 16];
            qhf[c][2] = *(const uint32_t*)&g_qh[r0 + c * 16 + 8];
            qhf[c][3] = *(const uint32_t*)&g_qh[r0 + 512 + c * 16 + 8];
        }
    }
    {
        size_t ko = ((size_t)h * L + (size_t)lut[0] * 64) * 64;
#pragma unroll
        for (int i = 0; i < 4; i++) {
            cp16(sb + soff[i], (const char*)(g_kh + ko) + goff[i]);
            cp16(sb + 8192 + soff[i], (const char*)(g_vt + ko) + goff[i]);
        }
    }
    cp_commit(); cp_wait0();
    __syncthreads();

    float oacc[8][4];
#pragma unroll
    for (int n = 0; n < 8; n++)
#pragma unroll
        for (int e = 0; e < 4; e++) oacc[n][e] = 0.f;
    float psum0 = 0.f, psum1 = 0.f;

    const uint32_t loff = (lane & 7) * 128;
    const uint32_t xt = (lane & 7) << 4;
    const uint32_t xh = (lane >> 3) * 16;

    for (int it = 0; it < 8; it++) {
        uint32_t cb = sb + ((it & 1) ? BUFSZ : 0);
        if (it + 1 < 8) {
            size_t ko = ((size_t)h * L + (size_t)lut[it + 1] * 64) * 64;
            uint32_t nb = sb + ((it & 1) ? 0 : BUFSZ);
#pragma unroll
            for (int i = 0; i < 4; i++) {
                cp16(nb + soff[i], (const char*)(g_kh + ko) + goff[i]);
                cp16(nb + 8192 + soff[i], (const char*)(g_vt + ko) + goff[i]);
            }
            cp_commit();
        }
        uint32_t pa[4][4];
#pragma unroll
        for (int kc = 0; kc < 4; kc++) {
#pragma unroll
            for (int jj = 0; jj < 2; jj++) {
                int j = 2 * kc + jj;
                float sa[4] = {0.f, 0.f, 0.f, 0.f};
                uint32_t ab = cb + j * 1024 + loff;
                uint32_t khf[8];
                ldsm4(ab + (xh ^ xt), khf[0], khf[1], khf[2], khf[3]);
                ldsm4(ab + ((64 + xh) ^ xt), khf[4], khf[5], khf[6], khf[7]);
#pragma unroll
                for (int c = 0; c < 4; c++)
                    mma_f16(sa, qhf[c], &khf[2 * c]);
                float p0 = __expf(sa[0] * 0.125f);
                float p1 = __expf(sa[1] * 0.125f);
                float p2 = __expf(sa[2] * 0.125f);
                float p3 = __expf(sa[3] * 0.125f);
                psum0 += p0 + p1; psum1 += p2 + p3;
                pa[kc][jj * 2] = pack_h2(p1, p0);
                pa[kc][jj * 2 + 1] = pack_h2(p3, p2);
            }
        }
        uint32_t vb = cb + 8192 + loff;
#pragma unroll
        for (int n = 0; n < 8; n++) {
            uint32_t vf[8];
            ldsm4(vb + n * 1024 + (xh ^ xt), vf[0], vf[1], vf[2], vf[3]);
            ldsm4(vb + n * 1024 + ((64 + xh) ^ xt), vf[4], vf[5], vf[6], vf[7]);
#pragma unroll
            for (int kc = 0; kc < 4; kc++)
                mma_f16(oacc[n], pa[kc], &vf[2 * kc]);
        }
        if (it + 1 < 8) cp_wait0();
        __syncthreads();
    }

    psum0 += __shfl_xor_sync(~0u, psum0, 1);
    psum0 += __shfl_xor_sync(~0u, psum0, 2);
    psum1 += __shfl_xor_sync(~0u, psum1, 1);
    psum1 += __shfl_xor_sync(~0u, psum1, 2);
    if ((lane & 3) == 0) {
        g_psum[idx * 64 + w * 16 + (lane >> 2)] = psum0;
        g_psum[idx * 64 + w * 16 + (lane >> 2) + 8] = psum1;
    }
    float inv0 = 1.f / psum0, inv1 = 1.f / psum1;
    __half* op = g_oparth + (size_t)idx * 4096 + (w * 16 + (lane >> 2)) * 64;
#pragma unroll
    for (int n = 0; n < 8; n++) {
        int c = n * 8 + (lane & 3) * 2;
        *(uint32_t*)(op + c) = pack_h2(oacc[n][1] * inv0, oacc[n][0] * inv0);
        *(uint32_t*)(op + 512 + c) = pack_h2(oacc[n][3] * inv1, oacc[n][2] * inv1);
    }
}

// ---------------- combine partials + linear branch (WRITES out) ----------------
__global__ __launch_bounds__(256)
void lin_out_kernel(const float* __restrict__ bias, float* __restrict__ out) {
    __shared__ float M_s[4096], ks_s[64], b_s[64];
    __shared__ float qf_s[8][64];
    int h = blockIdx.x >> 7, rb = blockIdx.x & 127;
    int t = threadIdx.x, w = t >> 5, lane = t & 31;
    for (int i = t; i < 4096; i += 256) M_s[i] = g_M[h * 4096 + i];
    if (t < 64) { ks_s[t] = g_ksum[h * 64 + t]; b_s[t] = bias[t]; }
    __syncthreads();
#pragma unroll
    for (int rr = 0; rr < 4; rr++) {
        int row = rb * 32 + w * 4 + rr;
        size_t grow = (size_t)h * L + row;
        int qb = row >> 6, rloc = row & 63;
        float qf0 = __half2float(g_qf[grow * 64 + lane]);
        float qf1 = __half2float(g_qf[grow * 64 + lane + 32]);
        float dn = qf0 * ks_s[lane] + qf1 * ks_s[lane + 32];
#pragma unroll
        for (int o = 16; o >= 1; o >>= 1) dn += __shfl_xor_sync(~0u, dn, o);
        dn += 1e-5f;
        qf_s[w][lane] = qf0; qf_s[w][lane + 32] = qf1;
        __syncwarp();
        float t0 = 0.f, t1 = 0.f;
#pragma unroll
        for (int dd = 0; dd < 64; dd++) {
            float qd = qf_s[w][dd];
            t0 += qd * M_s[dd * 64 + lane];
            t1 += qd * M_s[dd * 64 + lane + 32];
        }
        float invd = 1.f / dn;
        int pidx = (h * 64 + qb) * 2;
        size_t pb = (size_t)pidx * 4096 + rloc * 64;
        float sA = g_psum[pidx * 64 + rloc];
        float sB = g_psum[(pidx + 1) * 64 + rloc];
        float invs = 1.f / (sA + sB);
        float wA = sA * invs, wB = sB * invs;
        float s0 = __half2float(g_oparth[pb + lane]) * wA +
                   __half2float(g_oparth[pb + 4096 + lane]) * wB;
        float s1 = __half2float(g_oparth[pb + lane + 32]) * wA +
                   __half2float(g_oparth[pb + 4096 + lane + 32]) * wB;
        out[grow * 64 + lane] = s0 + t0 * invd + b_s[lane];
        out[grow * 64 + lane + 32] = s1 + t1 * invd + b_s[lane + 32];
    }
}

// ---------------- launch ----------------
extern "C" void kernel_launch(void* const* d_in, const int* in_sizes, int n_in,
                              void* d_out, int out_size) {
    const float* q = (const float*)d_in[0];
    const float* k = (const float*)d_in[1];
    const float* v = (const float*)d_in[2];
    const float* W = (const float*)d_in[3];
    const float* b = (const float*)d_in[4];
    float* out = (float*)d_out;

    prep_kernel<<<H * NB, 256>>>(q, k, v);        // 0
    topk_kernel<<<H * NB, 64>>>();                // 1
    kvacc_mma_kernel<<<H * KVP, 128>>>();         // 2
    cudaFuncSetAttribute(sparse_mma_kernel,
                         cudaFuncAttributeMaxDynamicSharedMemorySize, 2 * BUFSZ);
    sparse_mma_kernel<<<H * NB * 2, 128, 2 * BUFSZ>>>();   // 3 (profiled slot)
    kvmat_kernel<<<H * 8, 512>>>(W);              // 4
    lin_out_kernel<<<H * 128, 256>>>(b, out);     // 5
}